// round 1
// baseline (speedup 1.0000x reference)
#include <cuda_runtime.h>
#include <math.h>

#define BM 128
#define BN 256
#define BK 16
#define NTHREADS 512

// Fused hyperbolic linear layer:
//   tangent = atanh(min(0.1*||x||, 1-1e-6)) / (0.1*||x||) * x
//   v       = tangent @ W^T + b
//   res     = tanh(0.1*||v||) / (0.1*||v||) * v
//   out     = res * min(||res||, 10 - 2e-6) / ||res||
// The log-map scale is per-row, so it is applied AFTER the raw GEMM:
//   v[r][j] = xscale[r] * (x[r] . W[j]) + b[j]
__global__ __launch_bounds__(NTHREADS, 1)
void hyper_fused_kernel(const float* __restrict__ x,
                        const float* __restrict__ W,
                        const float* __restrict__ b,
                        float* __restrict__ out)
{
    __shared__ float As[BK][BM];      // x tile, K-major
    __shared__ float Bs[BK][BN];      // W tile, K-major
    __shared__ float xscale_s[BM];
    __shared__ float rnorm_s[BM];
    __shared__ float factor_s[BM];

    const int tid   = threadIdx.x;
    const int col_t = tid & 31;   // 0..31  (8 output cols each)
    const int row_t = tid >> 5;   // 0..15  (warp id == row group; 8 rows each)
    const long row0 = (long)blockIdx.x * BM;

    // ---------------- phase 0: log-map scale per row ----------------
    {
        const int q = tid & 3;        // quarter of row
        const int r = tid >> 2;       // 0..127
        const float4* xr = (const float4*)(x + (row0 + r) * 256);
        float s = 0.f;
        #pragma unroll
        for (int i = 0; i < 16; i++) {
            float4 v = xr[i * 4 + q];
            s += v.x * v.x + v.y * v.y + v.z * v.z + v.w * v.w;
        }
        s += __shfl_xor_sync(0xffffffffu, s, 1);
        s += __shfl_xor_sync(0xffffffffu, s, 2);
        if (q == 0) {
            float xn = fmaxf(sqrtf(s), 1e-6f);
            float scaled = fminf(0.1f * xn, 1.0f - 1e-6f);
            xscale_s[r] = atanhf(scaled) / (0.1f * xn);
        }
    }

    // bias values for this thread's 8 output columns
    float bv[8];
    {
        const float4* b4 = (const float4*)(b + col_t * 8);
        float4 t0 = b4[0], t1 = b4[1];
        bv[0] = t0.x; bv[1] = t0.y; bv[2] = t0.z; bv[3] = t0.w;
        bv[4] = t1.x; bv[5] = t1.y; bv[6] = t1.z; bv[7] = t1.w;
    }

    float acc[8][8];
    #pragma unroll
    for (int i = 0; i < 8; i++)
        #pragma unroll
        for (int j = 0; j < 8; j++) acc[i][j] = 0.f;

    // ---------------- phase 1: GEMM acc = x_tile @ W^T ----------------
    for (int kc = 0; kc < 256; kc += BK) {
        __syncthreads();
        // Load A tile: 128 rows x 16 k = 512 float4, one per thread
        {
            const int r  = tid >> 2;
            const int kq = tid & 3;
            float4 v = *(const float4*)(x + (row0 + r) * 256 + kc + kq * 4);
            As[kq * 4 + 0][r] = v.x;
            As[kq * 4 + 1][r] = v.y;
            As[kq * 4 + 2][r] = v.z;
            As[kq * 4 + 3][r] = v.w;
        }
        // Load B tile: 256 rows(j) x 16 k = 1024 float4, two per thread
        #pragma unroll
        for (int it = 0; it < 2; it++) {
            const int j  = (tid >> 2) + it * 128;
            const int kq = tid & 3;
            float4 v = *(const float4*)(W + (long)j * 256 + kc + kq * 4);
            Bs[kq * 4 + 0][j] = v.x;
            Bs[kq * 4 + 1][j] = v.y;
            Bs[kq * 4 + 2][j] = v.z;
            Bs[kq * 4 + 3][j] = v.w;
        }
        __syncthreads();

        #pragma unroll
        for (int kk = 0; kk < BK; kk++) {
            float a[8], bb[8];
            float4 a0 = *(const float4*)&As[kk][row_t * 8];
            float4 a1 = *(const float4*)&As[kk][row_t * 8 + 4];
            float4 c0 = *(const float4*)&Bs[kk][col_t * 8];
            float4 c1 = *(const float4*)&Bs[kk][col_t * 8 + 4];
            a[0] = a0.x; a[1] = a0.y; a[2] = a0.z; a[3] = a0.w;
            a[4] = a1.x; a[5] = a1.y; a[6] = a1.z; a[7] = a1.w;
            bb[0] = c0.x; bb[1] = c0.y; bb[2] = c0.z; bb[3] = c0.w;
            bb[4] = c1.x; bb[5] = c1.y; bb[6] = c1.z; bb[7] = c1.w;
            #pragma unroll
            for (int rr = 0; rr < 8; rr++)
                #pragma unroll
                for (int cc = 0; cc < 8; cc++)
                    acc[rr][cc] = fmaf(a[rr], bb[cc], acc[rr][cc]);
        }
    }

    // ---------------- phase 2: v = xscale*acc + b, row norms ----------------
    #pragma unroll
    for (int rr = 0; rr < 8; rr++) {
        const int row = row_t * 8 + rr;
        const float xs = xscale_s[row];   // broadcast within warp
        float s = 0.f;
        #pragma unroll
        for (int cc = 0; cc < 8; cc++) {
            float v = fmaf(acc[rr][cc], xs, bv[cc]);
            acc[rr][cc] = v;
            s = fmaf(v, v, s);
        }
        // full-warp reduce: all 32 lanes of this warp hold the same row set
        s += __shfl_xor_sync(0xffffffffu, s, 16);
        s += __shfl_xor_sync(0xffffffffu, s, 8);
        s += __shfl_xor_sync(0xffffffffu, s, 4);
        s += __shfl_xor_sync(0xffffffffu, s, 2);
        s += __shfl_xor_sync(0xffffffffu, s, 1);
        if (col_t == 0) rnorm_s[row] = s;
    }
    __syncthreads();

    // ---------------- phase 3: exp-map + projection factor per row ----------------
    if (tid < BM) {
        float vn = fmaxf(sqrtf(rnorm_s[tid]), 1e-6f);
        float g  = tanhf(0.1f * vn) / (0.1f * vn);   // res = g * v
        float rn = fmaxf(g * vn, 1e-6f);             // ||res||
        float clamped = fminf(rn, 10.0f - 2e-6f);    // (1/sqrt(c)-EPS)-EPS
        factor_s[tid] = g * (clamped / rn);
    }
    __syncthreads();

    // ---------------- phase 4: store ----------------
    #pragma unroll
    for (int rr = 0; rr < 8; rr++) {
        const int row = row_t * 8 + rr;
        const float f = factor_s[row];
        float4 o0, o1;
        o0.x = acc[rr][0] * f; o0.y = acc[rr][1] * f;
        o0.z = acc[rr][2] * f; o0.w = acc[rr][3] * f;
        o1.x = acc[rr][4] * f; o1.y = acc[rr][5] * f;
        o1.z = acc[rr][6] * f; o1.w = acc[rr][7] * f;
        float* orow = out + (row0 + row) * 256 + col_t * 8;
        *(float4*)(orow)     = o0;
        *(float4*)(orow + 4) = o1;
    }
}

extern "C" void kernel_launch(void* const* d_in, const int* in_sizes, int n_in,
                              void* d_out, int out_size)
{
    const float* x = (const float*)d_in[0];
    const float* W = (const float*)d_in[1];
    const float* b = (const float*)d_in[2];
    float* out = (float*)d_out;

    const int nrows = in_sizes[0] / 256;   // 262144
    dim3 grid(nrows / BM);
    hyper_fused_kernel<<<grid, NTHREADS>>>(x, W, b, out);
}

// round 3
// speedup vs baseline: 1.4573x; 1.4573x over previous
#include <cuda_runtime.h>
#include <cuda_bf16.h>
#include <math.h>

// ============================================================================
// Hyperbolic linear layer via mma.sync (HMMA bf16, fp32 acc), sm_103-safe PTX.
//   v   = xscale(row) * (x @ W^T) + b
//   out = proj(exp_map_zero(v))
// Split-bf16 3-term GEMM: x = xh+xl, W = Wh+Wl (bf16 each);
//   x@W^T ~= xh@Wh^T + xh@Wl^T + xl@Wh^T    (residual ~2^-17)
// ============================================================================

#define NT 512

// SMEM layout (bytes). Rows padded to 144B (128B data + 16B) => conflict-free
// ldmatrix with 8-row groups (bank = 4*r mod 32, distinct).
#define A_ST   18432            // 128 rows * 144B, per stage
#define B_ST   36864            // 256 rows * 144B, per stage
#define AHI    0                // 2 stages
#define ALO    36864            // 2 stages
#define BHI    73728            // 2 stages
#define BLO    147456           // 2 stages
#define CTRL   221184
#define SMEM_BYTES (CTRL + 4608)

// W split into bf16 hi/lo, plain [n][k] row-major (k contiguous, 512B rows).
__device__ __align__(16) unsigned short g_Whi[65536];
__device__ __align__(16) unsigned short g_Wlo[65536];

__global__ void prep_W_kernel(const float* __restrict__ W)
{
    int n = blockIdx.x, k = threadIdx.x;
    float w = W[n * 256 + k];
    __nv_bfloat16 hi = __float2bfloat16(w);
    float hif = __bfloat162float(hi);
    __nv_bfloat16 lo = __float2bfloat16(w - hif);
    g_Whi[n * 256 + k] = __bfloat16_as_ushort(hi);
    g_Wlo[n * 256 + k] = __bfloat16_as_ushort(lo);
}

// ---------------------------------------------------------------------------
__device__ __forceinline__ unsigned smem_u32(const void* p) {
    unsigned a;
    asm("{ .reg .u64 t; cvta.to.shared.u64 t, %1; cvt.u32.u64 %0, t; }"
        : "=r"(a) : "l"(p));
    return a;
}
__device__ __forceinline__ void cpasync16(unsigned dst, const void* src) {
    asm volatile("cp.async.cg.shared.global [%0], [%1], 16;"
                 :: "r"(dst), "l"(src));
}
#define CP_COMMIT() asm volatile("cp.async.commit_group;")
#define CP_WAIT0()  asm volatile("cp.async.wait_group 0;")

#define LDSM4(r, addr) \
    asm volatile("ldmatrix.sync.aligned.m8n8.x4.shared.b16 {%0,%1,%2,%3}, [%4];" \
        : "=r"((r)[0]), "=r"((r)[1]), "=r"((r)[2]), "=r"((r)[3]) : "r"(addr))

#define MMA(d, a, b0, b1) \
    asm volatile("mma.sync.aligned.m16n8k16.row.col.f32.bf16.bf16.f32 " \
        "{%0,%1,%2,%3}, {%4,%5,%6,%7}, {%8,%9}, {%0,%1,%2,%3};" \
        : "+f"((d)[0]), "+f"((d)[1]), "+f"((d)[2]), "+f"((d)[3]) \
        : "r"((a)[0]), "r"((a)[1]), "r"((a)[2]), "r"((a)[3]), "r"(b0), "r"(b1))

__device__ __forceinline__ unsigned pack_bf16x2(float lo, float hi) {
    unsigned r;
    asm("cvt.rn.bf16x2.f32 %0, %1, %2;" : "=r"(r) : "f"(hi), "f"(lo));
    return r;
}

// Convert 64-K chunk of x rows [row0, row0+128) to bf16 hi/lo in stage s.
// thread: r = tid>>2, seg = tid&3 (16 floats). Accumulates row sumsq.
__device__ __forceinline__ void convertA(char* sm, const float* __restrict__ x,
                                         long row0, int tid, int c, int s,
                                         float& ssx)
{
    const int r = tid >> 2, seg = tid & 3;
    const float4* src = (const float4*)(x + (row0 + r) * 256 + c * 64 + seg * 16);
    char* dH = sm + AHI + s * A_ST + r * 144 + seg * 32;
    char* dL = sm + ALO + s * A_ST + r * 144 + seg * 32;
    unsigned uh[8], ul[8];
    #pragma unroll
    for (int i = 0; i < 4; i++) {
        float4 v = src[i];
        ssx = fmaf(v.x, v.x, fmaf(v.y, v.y, fmaf(v.z, v.z, fmaf(v.w, v.w, ssx))));
        unsigned h0 = pack_bf16x2(v.x, v.y);
        unsigned h1 = pack_bf16x2(v.z, v.w);
        float hx = __uint_as_float(h0 << 16);
        float hy = __uint_as_float(h0 & 0xFFFF0000u);
        float hz = __uint_as_float(h1 << 16);
        float hw = __uint_as_float(h1 & 0xFFFF0000u);
        uh[2 * i]     = h0;
        uh[2 * i + 1] = h1;
        ul[2 * i]     = pack_bf16x2(v.x - hx, v.y - hy);
        ul[2 * i + 1] = pack_bf16x2(v.z - hz, v.w - hw);
    }
    ((uint4*)dH)[0] = make_uint4(uh[0], uh[1], uh[2], uh[3]);
    ((uint4*)dH)[1] = make_uint4(uh[4], uh[5], uh[6], uh[7]);
    ((uint4*)dL)[0] = make_uint4(ul[0], ul[1], ul[2], ul[3]);
    ((uint4*)dL)[1] = make_uint4(ul[4], ul[5], ul[6], ul[7]);
}

// Issue cp.async for B chunk c into stage s (hi + lo).
__device__ __forceinline__ void issueB(unsigned smb, int tid, int c, int s)
{
    #pragma unroll
    for (int i = 0; i < 4; i++) {
        int p = tid + i * NT;          // 0..2047
        int n = p >> 3, seg = p & 7;
        unsigned dst = smb + n * 144 + seg * 16 + s * B_ST;
        const char* srcH = (const char*)g_Whi + n * 512 + c * 128 + seg * 16;
        const char* srcL = (const char*)g_Wlo + n * 512 + c * 128 + seg * 16;
        cpasync16(dst + BHI, srcH);
        cpasync16(dst + BLO, srcL);
    }
}

__global__ __launch_bounds__(NT, 1)
void hyper_hmma_kernel(const float* __restrict__ x,
                       const float* __restrict__ bias,
                       float* __restrict__ out)
{
    extern __shared__ char sm[];
    const unsigned smb = smem_u32(sm);
    const int tid  = threadIdx.x;
    const int lane = tid & 31;
    const int wid  = tid >> 5;
    const int wm   = wid & 3;          // m group (32 rows)
    const int wn   = wid >> 2;         // n group (64 cols)
    const long row0 = (long)blockIdx.x * 128;

    float* b_s      = (float*)(sm + CTRL);          // 256
    float* xscale_s = (float*)(sm + CTRL + 1024);   // 128
    float* part_s   = (float*)(sm + CTRL + 2048);   // 512
    float* factor_s = (float*)(sm + CTRL + 4096);   // 128

    if (tid < 256) b_s[tid] = bias[tid];

    // ldmatrix base addresses (lane-dependent)
    const unsigned aHiB = smb + AHI + (wm * 32 + (lane & 15)) * 144 + (lane >> 4) * 16;
    const unsigned aLoB = aHiB + (ALO - AHI);
    const unsigned bHiB = smb + BHI + (wn * 64 + (lane & 15)) * 144 + (lane >> 4) * 16;
    const unsigned bLoB = bHiB + (BLO - BHI);

    float acc[16][4];
    #pragma unroll
    for (int i = 0; i < 16; i++)
        #pragma unroll
        for (int j = 0; j < 4; j++) acc[i][j] = 0.f;

    float ssx = 0.f;

    // prologue: chunk 0 -> stage 0
    issueB(smb, tid, 0, 0);
    CP_COMMIT();
    convertA(sm, x, row0, tid, 0, 0, ssx);

    // ------------------------- mainloop: 4 K-chunks -------------------------
    #pragma unroll 1
    for (int c = 0; c < 4; c++) {
        const int s = c & 1;
        CP_WAIT0();
        __syncthreads();
        if (c < 3) {                     // prefetch next chunk into other stage
            issueB(smb, tid, c + 1, s ^ 1);
            CP_COMMIT();
            convertA(sm, x, row0, tid, c + 1, s ^ 1, ssx);
        }
        const unsigned aH = aHiB + s * A_ST;
        const unsigned aL = aLoB + s * A_ST;
        const unsigned bH = bHiB + s * B_ST;
        const unsigned bL = bLoB + s * B_ST;
        #pragma unroll
        for (int k16 = 0; k16 < 4; k16++) {
            unsigned ah[2][4], al[2][4];
            #pragma unroll
            for (int mi = 0; mi < 2; mi++) {
                LDSM4(ah[mi], aH + mi * 2304 + k16 * 32);
                LDSM4(al[mi], aL + mi * 2304 + k16 * 32);
            }
            #pragma unroll
            for (int nn = 0; nn < 4; nn++) {
                unsigned bh[4], bl[4];
                LDSM4(bh, bH + nn * 2304 + k16 * 32);
                LDSM4(bl, bL + nn * 2304 + k16 * 32);
                #pragma unroll
                for (int mi = 0; mi < 2; mi++) {
                    #pragma unroll
                    for (int hn = 0; hn < 2; hn++) {
                        float* d = acc[mi * 8 + nn * 2 + hn];
                        MMA(d, ah[mi], bh[hn], bh[hn + 2]);
                        MMA(d, ah[mi], bl[hn], bl[hn + 2]);
                        MMA(d, al[mi], bh[hn], bh[hn + 2]);
                    }
                }
            }
        }
    }

    // log-map scale per row (4 lanes share row r = tid>>2)
    {
        float t = ssx;
        t += __shfl_xor_sync(0xffffffffu, t, 1);
        t += __shfl_xor_sync(0xffffffffu, t, 2);
        if ((tid & 3) == 0) {
            float xn = fmaxf(sqrtf(t), 1e-6f);
            float sc = fminf(0.1f * xn, 1.0f - 1e-6f);
            xscale_s[tid >> 2] = atanhf(sc) / (0.1f * xn);
        }
    }
    __syncthreads();

    // ------------------------- epilogue -------------------------
    // acc[mi*8+nn*2+hn][j]: row = wm*32 + mi*16 + (j>=2)*8 + lane/4
    //                       col = wn*64 + (nn*2+hn)*8 + (lane&3)*2 + (j&1)
    const int rsub = lane >> 2;
    float xs[2][2];
    #pragma unroll
    for (int mi = 0; mi < 2; mi++)
        #pragma unroll
        for (int h = 0; h < 2; h++)
            xs[mi][h] = xscale_s[wm * 32 + mi * 16 + h * 8 + rsub];

    float2 bb[8];
    #pragma unroll
    for (int ni = 0; ni < 8; ni++) {
        int col = wn * 64 + ni * 8 + (lane & 3) * 2;
        bb[ni] = make_float2(b_s[col], b_s[col + 1]);
    }

    float ss[2][2] = {{0.f, 0.f}, {0.f, 0.f}};
    #pragma unroll
    for (int mi = 0; mi < 2; mi++) {
        #pragma unroll
        for (int ni = 0; ni < 8; ni++) {
            float* d = acc[mi * 8 + ni];
            float v0 = fmaf(d[0], xs[mi][0], bb[ni].x);
            float v1 = fmaf(d[1], xs[mi][0], bb[ni].y);
            float v2 = fmaf(d[2], xs[mi][1], bb[ni].x);
            float v3 = fmaf(d[3], xs[mi][1], bb[ni].y);
            d[0] = v0; d[1] = v1; d[2] = v2; d[3] = v3;
            ss[mi][0] = fmaf(v0, v0, fmaf(v1, v1, ss[mi][0]));
            ss[mi][1] = fmaf(v2, v2, fmaf(v3, v3, ss[mi][1]));
        }
    }
    #pragma unroll
    for (int mi = 0; mi < 2; mi++)
        #pragma unroll
        for (int h = 0; h < 2; h++) {
            float t = ss[mi][h];
            t += __shfl_xor_sync(0xffffffffu, t, 1);
            t += __shfl_xor_sync(0xffffffffu, t, 2);
            if ((lane & 3) == 0)
                part_s[wn * 128 + wm * 32 + mi * 16 + h * 8 + rsub] = t;
        }
    __syncthreads();
    if (tid < 128) {
        float tot = part_s[tid] + part_s[128 + tid] + part_s[256 + tid] + part_s[384 + tid];
        float vn = fmaxf(sqrtf(tot), 1e-6f);
        float g  = tanhf(0.1f * vn) / (0.1f * vn);
        float rn = fmaxf(g * vn, 1e-6f);
        float cl = fminf(rn, 10.0f - 2e-6f);
        factor_s[tid] = g * (cl / rn);
    }
    __syncthreads();

    #pragma unroll
    for (int mi = 0; mi < 2; mi++) {
        #pragma unroll
        for (int h = 0; h < 2; h++) {
            const int row = wm * 32 + mi * 16 + h * 8 + rsub;
            const float f = factor_s[row];
            float* orow = out + (row0 + row) * 256;
            #pragma unroll
            for (int ni = 0; ni < 8; ni++) {
                float* d = acc[mi * 8 + ni];
                int col = wn * 64 + ni * 8 + (lane & 3) * 2;
                float2 o;
                o.x = d[h * 2]     * f;
                o.y = d[h * 2 + 1] * f;
                *(float2*)(orow + col) = o;
            }
        }
    }
}

extern "C" void kernel_launch(void* const* d_in, const int* in_sizes, int n_in,
                              void* d_out, int out_size)
{
    const float* x = (const float*)d_in[0];
    const float* W = (const float*)d_in[1];
    const float* b = (const float*)d_in[2];
    float* out = (float*)d_out;

    prep_W_kernel<<<256, 256>>>(W);

    cudaFuncSetAttribute(hyper_hmma_kernel,
                         cudaFuncAttributeMaxDynamicSharedMemorySize, SMEM_BYTES);
    const int nrows = in_sizes[0] / 256;
    hyper_hmma_kernel<<<nrows / 128, NT, SMEM_BYTES>>>(x, b, out);
}

// round 4
// speedup vs baseline: 2.1496x; 1.4751x over previous
#include <cuda_runtime.h>
#include <cuda_bf16.h>
#include <math.h>

// ============================================================================
// Hyperbolic linear layer via mma.sync (HMMA bf16, fp32 acc), sm_103-safe PTX.
//   v   = xscale(row) * (x @ W^T) + b ;  out = proj(exp_map_zero(v))
// Split-bf16 3-term GEMM: x@W^T ~= xh@Wh^T + xh@Wl^T + xl@Wh^T  (err ~2^-17)
// R4: raw-A staged in SMEM via cp.async; conversion moved off critical path.
// ============================================================================

#define NT 512

// SMEM layout (bytes)
#define RAW_OFF 0                 // raw fp32 A chunk: 128 rows * 304B = 38912
#define RAW_STRIDE 304
#define AHI     38912             // conv A hi: 128 rows * 144B = 18432
#define ALO     57344             // conv A lo: 18432
#define B_ST    36864             // 256 rows * 144B per stage
#define BHI     75776             // 2 stages
#define BLO     149504            // 2 stages
#define CTRL    223232
#define SMEM_BYTES (CTRL + 4096)

// W split into bf16 hi/lo, [n][k] row-major.
__device__ __align__(16) unsigned short g_Whi[65536];
__device__ __align__(16) unsigned short g_Wlo[65536];

__global__ void prep_W_kernel(const float* __restrict__ W)
{
    int n = blockIdx.x, k = threadIdx.x;
    float w = W[n * 256 + k];
    __nv_bfloat16 hi = __float2bfloat16(w);
    float hif = __bfloat162float(hi);
    __nv_bfloat16 lo = __float2bfloat16(w - hif);
    g_Whi[n * 256 + k] = __bfloat16_as_ushort(hi);
    g_Wlo[n * 256 + k] = __bfloat16_as_ushort(lo);
}

// ---------------------------------------------------------------------------
__device__ __forceinline__ unsigned smem_u32(const void* p) {
    unsigned a;
    asm("{ .reg .u64 t; cvta.to.shared.u64 t, %1; cvt.u32.u64 %0, t; }"
        : "=r"(a) : "l"(p));
    return a;
}
__device__ __forceinline__ void cpasync16(unsigned dst, const void* src) {
    asm volatile("cp.async.cg.shared.global [%0], [%1], 16;"
                 :: "r"(dst), "l"(src));
}
#define CP_COMMIT() asm volatile("cp.async.commit_group;")
#define CP_WAIT0()  asm volatile("cp.async.wait_group 0;")
#define CP_WAIT1()  asm volatile("cp.async.wait_group 1;")

#define LDSM4(r, addr) \
    asm volatile("ldmatrix.sync.aligned.m8n8.x4.shared.b16 {%0,%1,%2,%3}, [%4];" \
        : "=r"((r)[0]), "=r"((r)[1]), "=r"((r)[2]), "=r"((r)[3]) : "r"(addr))

#define MMA(d, a, b0, b1) \
    asm volatile("mma.sync.aligned.m16n8k16.row.col.f32.bf16.bf16.f32 " \
        "{%0,%1,%2,%3}, {%4,%5,%6,%7}, {%8,%9}, {%0,%1,%2,%3};" \
        : "+f"((d)[0]), "+f"((d)[1]), "+f"((d)[2]), "+f"((d)[3]) \
        : "r"((a)[0]), "r"((a)[1]), "r"((a)[2]), "r"((a)[3]), "r"(b0), "r"(b1))

__device__ __forceinline__ unsigned pack_bf16x2(float lo, float hi) {
    unsigned r;
    asm("cvt.rn.bf16x2.f32 %0, %1, %2;" : "=r"(r) : "f"(hi), "f"(lo));
    return r;
}

// cp.async raw fp32 A chunk c -> RAW staging.  2048 x 16B, 4 per thread.
__device__ __forceinline__ void issueRawA(unsigned smb, const float* __restrict__ x,
                                          long row0, int tid, int c)
{
    #pragma unroll
    for (int i = 0; i < 4; i++) {
        int p = tid + i * NT;
        int r = p & 127, s16 = p >> 7;             // 16B block within row
        unsigned dst = smb + RAW_OFF + r * RAW_STRIDE + s16 * 16;
        const float* src = x + (row0 + r) * 256 + c * 64 + s16 * 4;
        cpasync16(dst, src);
    }
}

// cp.async B chunk c into stage s (hi + lo).
__device__ __forceinline__ void issueB(unsigned smb, int tid, int c, int s)
{
    #pragma unroll
    for (int i = 0; i < 4; i++) {
        int p = tid + i * NT;          // 0..2047
        int n = p >> 3, seg = p & 7;
        unsigned dst = smb + n * 144 + seg * 16 + s * B_ST;
        cpasync16(dst + BHI, (const char*)g_Whi + n * 512 + c * 128 + seg * 16);
        cpasync16(dst + BLO, (const char*)g_Wlo + n * 512 + c * 128 + seg * 16);
    }
}

// Convert staged raw A -> bf16 hi/lo conv buffers. thread: row r = tid&127,
// seg = tid>>7 (16 floats). LDS phases conflict-free (stride 304B = 76 words).
__device__ __forceinline__ void convertA(char* sm, int tid, float& ssx)
{
    const int r = tid & 127, seg = tid >> 7;
    const char* src = sm + RAW_OFF + r * RAW_STRIDE + seg * 64;
    char* dH = sm + AHI + r * 144 + seg * 32;
    char* dL = sm + ALO + r * 144 + seg * 32;
    unsigned uh[8], ul[8];
    #pragma unroll
    for (int i = 0; i < 4; i++) {
        float4 v = *(const float4*)(src + i * 16);
        ssx = fmaf(v.x, v.x, fmaf(v.y, v.y, fmaf(v.z, v.z, fmaf(v.w, v.w, ssx))));
        unsigned h0 = pack_bf16x2(v.x, v.y);
        unsigned h1 = pack_bf16x2(v.z, v.w);
        float hx = __uint_as_float(h0 << 16);
        float hy = __uint_as_float(h0 & 0xFFFF0000u);
        float hz = __uint_as_float(h1 << 16);
        float hw = __uint_as_float(h1 & 0xFFFF0000u);
        uh[2 * i]     = h0;
        uh[2 * i + 1] = h1;
        ul[2 * i]     = pack_bf16x2(v.x - hx, v.y - hy);
        ul[2 * i + 1] = pack_bf16x2(v.z - hz, v.w - hw);
    }
    ((uint4*)dH)[0] = make_uint4(uh[0], uh[1], uh[2], uh[3]);
    ((uint4*)dH)[1] = make_uint4(uh[4], uh[5], uh[6], uh[7]);
    ((uint4*)dL)[0] = make_uint4(ul[0], ul[1], ul[2], ul[3]);
    ((uint4*)dL)[1] = make_uint4(ul[4], ul[5], ul[6], ul[7]);
}

__global__ __launch_bounds__(NT, 1)
void hyper_hmma_kernel(const float* __restrict__ x,
                       const float* __restrict__ bias,
                       float* __restrict__ out)
{
    extern __shared__ char sm[];
    const unsigned smb = smem_u32(sm);
    const int tid  = threadIdx.x;
    const int lane = tid & 31;
    const int wid  = tid >> 5;
    const int wm   = wid & 3;          // m group (32 rows)
    const int wn   = wid >> 2;         // n group (64 cols)
    const long row0 = (long)blockIdx.x * 128;

    float* b_s      = (float*)(sm + CTRL);          // 256 f
    float* xscale_s = (float*)(sm + CTRL + 1024);   // 128 f
    float* part_s   = (float*)(sm + CTRL + 1536);   // 512 f
    float* factor_s = (float*)(sm + CTRL + 3584);   // 128 f

    if (tid < 256) b_s[tid] = bias[tid];

    const unsigned aHiB = smb + AHI + (wm * 32 + (lane & 15)) * 144 + (lane >> 4) * 16;
    const unsigned aLoB = aHiB + (ALO - AHI);
    const unsigned bHiB = smb + BHI + (wn * 64 + (lane & 15)) * 144 + (lane >> 4) * 16;
    const unsigned bLoB = bHiB + (BLO - BHI);

    float acc[16][4];
    #pragma unroll
    for (int i = 0; i < 16; i++)
        #pragma unroll
        for (int j = 0; j < 4; j++) acc[i][j] = 0.f;

    float ssx = 0.f;

    // prologue: raw A chunk0, then B chunk0 (separate groups, raw first)
    issueRawA(smb, x, row0, tid, 0);
    CP_COMMIT();
    issueB(smb, tid, 0, 0);
    CP_COMMIT();
    CP_WAIT1();                       // raw0 landed (B0 still in flight)
    __syncthreads();
    convertA(sm, tid, ssx);

    // ------------------------- mainloop: 4 K-chunks -------------------------
    #pragma unroll 1
    for (int c = 0; c < 4; c++) {
        const int s = c & 1;
        CP_WAIT0();                   // B(c) landed
        __syncthreads();              // convA(c) stores + B visible
        if (c < 3) {
            issueRawA(smb, x, row0, tid, c + 1);
            CP_COMMIT();
            issueB(smb, tid, c + 1, s ^ 1);
            CP_COMMIT();
        }
        const unsigned bH = bHiB + s * B_ST;
        const unsigned bL = bLoB + s * B_ST;
        #pragma unroll
        for (int k16 = 0; k16 < 4; k16++) {
            unsigned ah[2][4], al[2][4];
            #pragma unroll
            for (int mi = 0; mi < 2; mi++) {
                LDSM4(ah[mi], aHiB + mi * 2304 + k16 * 32);
                LDSM4(al[mi], aLoB + mi * 2304 + k16 * 32);
            }
            #pragma unroll
            for (int nn = 0; nn < 4; nn++) {
                unsigned bh[4], bl[4];
                LDSM4(bh, bH + nn * 2304 + k16 * 32);
                LDSM4(bl, bL + nn * 2304 + k16 * 32);
                #pragma unroll
                for (int mi = 0; mi < 2; mi++) {
                    #pragma unroll
                    for (int hn = 0; hn < 2; hn++) {
                        float* d = acc[mi * 8 + nn * 2 + hn];
                        MMA(d, ah[mi], bh[hn], bh[hn + 2]);
                        MMA(d, ah[mi], bl[hn], bl[hn + 2]);
                        MMA(d, al[mi], bh[hn], bh[hn + 2]);
                    }
                }
            }
        }
        if (c < 3) {
            CP_WAIT1();               // raw(c+1) landed (B(c+1) may still fly)
            __syncthreads();          // all warps done reading convA(c)
            convertA(sm, tid, ssx);   // overwrite convA with chunk c+1
        }
    }

    // log-map scale per row: ssx partials live on threads r, r+128, r+256, r+384
    part_s[tid] = ssx;
    __syncthreads();
    if (tid < 128) {
        float t = part_s[tid] + part_s[tid + 128] + part_s[tid + 256] + part_s[tid + 384];
        float xn = fmaxf(sqrtf(t), 1e-6f);
        float sc = fminf(0.1f * xn, 1.0f - 1e-6f);
        xscale_s[tid] = atanhf(sc) / (0.1f * xn);
    }
    __syncthreads();

    // ------------------------- epilogue -------------------------
    const int rsub = lane >> 2;
    float xs[2][2];
    #pragma unroll
    for (int mi = 0; mi < 2; mi++)
        #pragma unroll
        for (int h = 0; h < 2; h++)
            xs[mi][h] = xscale_s[wm * 32 + mi * 16 + h * 8 + rsub];

    float2 bb[8];
    #pragma unroll
    for (int ni = 0; ni < 8; ni++) {
        int col = wn * 64 + ni * 8 + (lane & 3) * 2;
        bb[ni] = make_float2(b_s[col], b_s[col + 1]);
    }

    float ss[2][2] = {{0.f, 0.f}, {0.f, 0.f}};
    #pragma unroll
    for (int mi = 0; mi < 2; mi++) {
        #pragma unroll
        for (int ni = 0; ni < 8; ni++) {
            float* d = acc[mi * 8 + ni];
            float v0 = fmaf(d[0], xs[mi][0], bb[ni].x);
            float v1 = fmaf(d[1], xs[mi][0], bb[ni].y);
            float v2 = fmaf(d[2], xs[mi][1], bb[ni].x);
            float v3 = fmaf(d[3], xs[mi][1], bb[ni].y);
            d[0] = v0; d[1] = v1; d[2] = v2; d[3] = v3;
            ss[mi][0] = fmaf(v0, v0, fmaf(v1, v1, ss[mi][0]));
            ss[mi][1] = fmaf(v2, v2, fmaf(v3, v3, ss[mi][1]));
        }
    }
    __syncthreads();   // xscale reads done before part_s reuse
    #pragma unroll
    for (int mi = 0; mi < 2; mi++)
        #pragma unroll
        for (int h = 0; h < 2; h++) {
            float t = ss[mi][h];
            t += __shfl_xor_sync(0xffffffffu, t, 1);
            t += __shfl_xor_sync(0xffffffffu, t, 2);
            if ((lane & 3) == 0)
                part_s[wn * 128 + wm * 32 + mi * 16 + h * 8 + rsub] = t;
        }
    __syncthreads();
    if (tid < 128) {
        float tot = part_s[tid] + part_s[128 + tid] + part_s[256 + tid] + part_s[384 + tid];
        float vn = fmaxf(sqrtf(tot), 1e-6f);
        float g  = tanhf(0.1f * vn) / (0.1f * vn);
        float rn = fmaxf(g * vn, 1e-6f);
        float cl = fminf(rn, 10.0f - 2e-6f);
        factor_s[tid] = g * (cl / rn);
    }
    __syncthreads();

    #pragma unroll
    for (int mi = 0; mi < 2; mi++) {
        #pragma unroll
        for (int h = 0; h < 2; h++) {
            const int row = wm * 32 + mi * 16 + h * 8 + rsub;
            const float f = factor_s[row];
            float* orow = out + (row0 + row) * 256;
            #pragma unroll
            for (int ni = 0; ni < 8; ni++) {
                float* d = acc[mi * 8 + ni];
                int col = wn * 64 + ni * 8 + (lane & 3) * 2;
                float2 o;
                o.x = d[h * 2]     * f;
                o.y = d[h * 2 + 1] * f;
                *(float2*)(orow + col) = o;
            }
        }
    }
}

extern "C" void kernel_launch(void* const* d_in, const int* in_sizes, int n_in,
                              void* d_out, int out_size)
{
    const float* x = (const float*)d_in[0];
    const float* W = (const float*)d_in[1];
    const float* b = (const float*)d_in[2];
    float* out = (float*)d_out;

    prep_W_kernel<<<256, 256>>>(W);

    cudaFuncSetAttribute(hyper_hmma_kernel,
                         cudaFuncAttributeMaxDynamicSharedMemorySize, SMEM_BYTES);
    const int nrows = in_sizes[0] / 256;
    hyper_hmma_kernel<<<nrows / 128, NT, SMEM_BYTES>>>(x, b, out);
}

// round 5
// speedup vs baseline: 2.2715x; 1.0567x over previous
#include <cuda_runtime.h>
#include <cuda_bf16.h>
#include <math.h>

// ============================================================================
// Hyperbolic linear layer via mma.sync (HMMA bf16, fp32 acc), sm_103-safe PTX.
//   v   = xscale(row) * (x @ W^T) + b ;  out = proj(exp_map_zero(v))
// Split-bf16 3-term GEMM: x@W^T ~= xh@Wh^T + xh@Wl^T + xl@Wh^T  (err ~2^-17)
// R5: converted-A double-buffered; conversion interleaved INTO the MMA loop
//     (LDG regs -> cvt -> STS in the MMA shadow). One sync per chunk.
// ============================================================================

#define NT 512

// SMEM layout (bytes)
#define A_ST 18432               // 128 rows * 144B per stage
#define B_ST 36864               // 256 rows * 144B per stage
#define AHI  0                   // 2 stages
#define ALO  36864               // 2 stages
#define BHI  73728               // 2 stages
#define BLO  147456              // 2 stages
#define CTRL 221184
#define SMEM_BYTES (CTRL + 4096)

// W split into bf16 hi/lo, [n][k] row-major.
__device__ __align__(16) unsigned short g_Whi[65536];
__device__ __align__(16) unsigned short g_Wlo[65536];

__global__ void prep_W_kernel(const float* __restrict__ W)
{
    int n = blockIdx.x, k = threadIdx.x;
    float w = W[n * 256 + k];
    __nv_bfloat16 hi = __float2bfloat16(w);
    float hif = __bfloat162float(hi);
    __nv_bfloat16 lo = __float2bfloat16(w - hif);
    g_Whi[n * 256 + k] = __bfloat16_as_ushort(hi);
    g_Wlo[n * 256 + k] = __bfloat16_as_ushort(lo);
}

// ---------------------------------------------------------------------------
__device__ __forceinline__ unsigned smem_u32(const void* p) {
    unsigned a;
    asm("{ .reg .u64 t; cvta.to.shared.u64 t, %1; cvt.u32.u64 %0, t; }"
        : "=r"(a) : "l"(p));
    return a;
}
__device__ __forceinline__ void cpasync16(unsigned dst, const void* src) {
    asm volatile("cp.async.cg.shared.global [%0], [%1], 16;"
                 :: "r"(dst), "l"(src));
}
#define CP_COMMIT() asm volatile("cp.async.commit_group;")
#define CP_WAIT0()  asm volatile("cp.async.wait_group 0;")

#define LDSM4(r, addr) \
    asm volatile("ldmatrix.sync.aligned.m8n8.x4.shared.b16 {%0,%1,%2,%3}, [%4];" \
        : "=r"((r)[0]), "=r"((r)[1]), "=r"((r)[2]), "=r"((r)[3]) : "r"(addr))

#define MMA(d, a, b0, b1) \
    asm volatile("mma.sync.aligned.m16n8k16.row.col.f32.bf16.bf16.f32 " \
        "{%0,%1,%2,%3}, {%4,%5,%6,%7}, {%8,%9}, {%0,%1,%2,%3};" \
        : "+f"((d)[0]), "+f"((d)[1]), "+f"((d)[2]), "+f"((d)[3]) \
        : "r"((a)[0]), "r"((a)[1]), "r"((a)[2]), "r"((a)[3]), "r"(b0), "r"(b1))

__device__ __forceinline__ unsigned pack_bf16x2(float lo, float hi) {
    unsigned r;
    asm("cvt.rn.bf16x2.f32 %0, %1, %2;" : "=r"(r) : "f"(hi), "f"(lo));
    return r;
}

// cp.async B chunk c into stage s (hi + lo).
__device__ __forceinline__ void issueB(unsigned smb, int tid, int c, int s)
{
    #pragma unroll
    for (int i = 0; i < 4; i++) {
        int p = tid + i * NT;          // 0..2047
        int n = p >> 3, seg = p & 7;
        unsigned dst = smb + n * 144 + seg * 16 + s * B_ST;
        cpasync16(dst + BHI, (const char*)g_Whi + n * 512 + c * 128 + seg * 16);
        cpasync16(dst + BLO, (const char*)g_Wlo + n * 512 + c * 128 + seg * 16);
    }
}

// Convert 16 fp32 (4x float4, this thread's slice of a K-chunk) into bf16
// hi/lo stage s. thread: row r = tid>>2, seg = tid&3. STS conflict-free.
__device__ __forceinline__ void convertRegs(char* sm, int tid, int s,
                                            const float4* v4, float& ssx)
{
    const int r = tid >> 2, seg = tid & 3;
    char* dH = sm + AHI + s * A_ST + r * 144 + seg * 32;
    char* dL = sm + ALO + s * A_ST + r * 144 + seg * 32;
    unsigned uh[8], ul[8];
    #pragma unroll
    for (int i = 0; i < 4; i++) {
        float4 v = v4[i];
        ssx = fmaf(v.x, v.x, fmaf(v.y, v.y, fmaf(v.z, v.z, fmaf(v.w, v.w, ssx))));
        unsigned h0 = pack_bf16x2(v.x, v.y);
        unsigned h1 = pack_bf16x2(v.z, v.w);
        float hx = __uint_as_float(h0 << 16);
        float hy = __uint_as_float(h0 & 0xFFFF0000u);
        float hz = __uint_as_float(h1 << 16);
        float hw = __uint_as_float(h1 & 0xFFFF0000u);
        uh[2 * i]     = h0;
        uh[2 * i + 1] = h1;
        ul[2 * i]     = pack_bf16x2(v.x - hx, v.y - hy);
        ul[2 * i + 1] = pack_bf16x2(v.z - hz, v.w - hw);
    }
    ((uint4*)dH)[0] = make_uint4(uh[0], uh[1], uh[2], uh[3]);
    ((uint4*)dH)[1] = make_uint4(uh[4], uh[5], uh[6], uh[7]);
    ((uint4*)dL)[0] = make_uint4(ul[0], ul[1], ul[2], ul[3]);
    ((uint4*)dL)[1] = make_uint4(ul[4], ul[5], ul[6], ul[7]);
}

__global__ __launch_bounds__(NT, 1)
void hyper_hmma_kernel(const float* __restrict__ x,
                       const float* __restrict__ bias,
                       float* __restrict__ out)
{
    extern __shared__ char sm[];
    const unsigned smb = smem_u32(sm);
    const int tid  = threadIdx.x;
    const int lane = tid & 31;
    const int wid  = tid >> 5;
    const int wm   = wid & 3;          // m group (32 rows)
    const int wn   = wid >> 2;         // n group (64 cols)
    const long row0 = (long)blockIdx.x * 128;

    float* b_s      = (float*)(sm + CTRL);          // 256 f
    float* xscale_s = (float*)(sm + CTRL + 1024);   // 128 f
    float* part_s   = (float*)(sm + CTRL + 1536);   // 512 f
    float* factor_s = (float*)(sm + CTRL + 3584);   // 128 f

    if (tid < 256) b_s[tid] = bias[tid];

    const unsigned aHiB = smb + AHI + (wm * 32 + (lane & 15)) * 144 + (lane >> 4) * 16;
    const unsigned aLoB = aHiB + (ALO - AHI);
    const unsigned bHiB = smb + BHI + (wn * 64 + (lane & 15)) * 144 + (lane >> 4) * 16;
    const unsigned bLoB = bHiB + (BLO - BHI);

    // A load geometry for this thread (row r, 16-float segment seg)
    const int ar = tid >> 2, aseg = tid & 3;
    const float* aptr = x + (row0 + ar) * 256 + aseg * 16;

    float acc[16][4];
    #pragma unroll
    for (int i = 0; i < 16; i++)
        #pragma unroll
        for (int j = 0; j < 4; j++) acc[i][j] = 0.f;

    float ssx = 0.f;

    // prologue: B0 in flight; convert A chunk0 from LDG regs into stage 0.
    issueB(smb, tid, 0, 0);
    CP_COMMIT();
    {
        float4 a0[4];
        #pragma unroll
        for (int i = 0; i < 4; i++) a0[i] = *(const float4*)(aptr + i * 4);
        convertRegs(sm, tid, 0, a0, ssx);
    }

    // ------------------------- mainloop: 4 K-chunks -------------------------
    #pragma unroll 1
    for (int c = 0; c < 4; c++) {
        const int s = c & 1;
        CP_WAIT0();                   // B(c) landed
        __syncthreads();              // B(c) + convA(c) visible to all

        float4 anx[4];
        if (c < 3) {
            issueB(smb, tid, c + 1, s ^ 1);
            CP_COMMIT();
            const float* ap = aptr + (c + 1) * 64;
            #pragma unroll
            for (int i = 0; i < 4; i++) anx[i] = *(const float4*)(ap + i * 4);
        }

        const unsigned aH = aHiB + s * A_ST;
        const unsigned aL = aLoB + s * A_ST;
        const unsigned bH = bHiB + s * B_ST;
        const unsigned bL = bLoB + s * B_ST;
        #pragma unroll
        for (int k16 = 0; k16 < 4; k16++) {
            unsigned ah[2][4], al[2][4];
            #pragma unroll
            for (int mi = 0; mi < 2; mi++) {
                LDSM4(ah[mi], aH + mi * 2304 + k16 * 32);
                LDSM4(al[mi], aL + mi * 2304 + k16 * 32);
            }
            #pragma unroll
            for (int nn = 0; nn < 4; nn++) {
                unsigned bh[4], bl[4];
                LDSM4(bh, bH + nn * 2304 + k16 * 32);
                LDSM4(bl, bL + nn * 2304 + k16 * 32);
                #pragma unroll
                for (int mi = 0; mi < 2; mi++) {
                    #pragma unroll
                    for (int hn = 0; hn < 2; hn++) {
                        float* d = acc[mi * 8 + nn * 2 + hn];
                        MMA(d, ah[mi], bh[hn], bh[hn + 2]);
                        MMA(d, ah[mi], bl[hn], bl[hn + 2]);
                        MMA(d, al[mi], bh[hn], bh[hn + 2]);
                    }
                }
            }
            // mid-loop: convert next-chunk A regs into the other stage
            if (k16 == 1 && c < 3)
                convertRegs(sm, tid, s ^ 1, anx, ssx);
        }
    }

    // log-map scale per row (4 lanes share row ar)
    {
        float t = ssx;
        t += __shfl_xor_sync(0xffffffffu, t, 1);
        t += __shfl_xor_sync(0xffffffffu, t, 2);
        if ((tid & 3) == 0) {
            float xn = fmaxf(sqrtf(t), 1e-6f);
            float sc = fminf(0.1f * xn, 1.0f - 1e-6f);
            xscale_s[ar] = atanhf(sc) / (0.1f * xn);
        }
    }
    __syncthreads();

    // ------------------------- epilogue -------------------------
    const int rsub = lane >> 2;
    float xs[2][2];
    #pragma unroll
    for (int mi = 0; mi < 2; mi++)
        #pragma unroll
        for (int h = 0; h < 2; h++)
            xs[mi][h] = xscale_s[wm * 32 + mi * 16 + h * 8 + rsub];

    float2 bb[8];
    #pragma unroll
    for (int ni = 0; ni < 8; ni++) {
        int col = wn * 64 + ni * 8 + (lane & 3) * 2;
        bb[ni] = make_float2(b_s[col], b_s[col + 1]);
    }

    float ss[2][2] = {{0.f, 0.f}, {0.f, 0.f}};
    #pragma unroll
    for (int mi = 0; mi < 2; mi++) {
        #pragma unroll
        for (int ni = 0; ni < 8; ni++) {
            float* d = acc[mi * 8 + ni];
            float v0 = fmaf(d[0], xs[mi][0], bb[ni].x);
            float v1 = fmaf(d[1], xs[mi][0], bb[ni].y);
            float v2 = fmaf(d[2], xs[mi][1], bb[ni].x);
            float v3 = fmaf(d[3], xs[mi][1], bb[ni].y);
            d[0] = v0; d[1] = v1; d[2] = v2; d[3] = v3;
            ss[mi][0] = fmaf(v0, v0, fmaf(v1, v1, ss[mi][0]));
            ss[mi][1] = fmaf(v2, v2, fmaf(v3, v3, ss[mi][1]));
        }
    }
    #pragma unroll
    for (int mi = 0; mi < 2; mi++)
        #pragma unroll
        for (int h = 0; h < 2; h++) {
            float t = ss[mi][h];
            t += __shfl_xor_sync(0xffffffffu, t, 1);
            t += __shfl_xor_sync(0xffffffffu, t, 2);
            if ((lane & 3) == 0)
                part_s[wn * 128 + wm * 32 + mi * 16 + h * 8 + rsub] = t;
        }
    __syncthreads();
    if (tid < 128) {
        float tot = part_s[tid] + part_s[128 + tid] + part_s[256 + tid] + part_s[384 + tid];
        float vn = fmaxf(sqrtf(tot), 1e-6f);
        float g  = tanhf(0.1f * vn) / (0.1f * vn);
        float rn = fmaxf(g * vn, 1e-6f);
        float cl = fminf(rn, 10.0f - 2e-6f);
        factor_s[tid] = g * (cl / rn);
    }
    __syncthreads();

    #pragma unroll
    for (int mi = 0; mi < 2; mi++) {
        #pragma unroll
        for (int h = 0; h < 2; h++) {
            const int row = wm * 32 + mi * 16 + h * 8 + rsub;
            const float f = factor_s[row];
            float* orow = out + (row0 + row) * 256;
            #pragma unroll
            for (int ni = 0; ni < 8; ni++) {
                float* d = acc[mi * 8 + ni];
                int col = wn * 64 + ni * 8 + (lane & 3) * 2;
                float2 o;
                o.x = d[h * 2]     * f;
                o.y = d[h * 2 + 1] * f;
                *(float2*)(orow + col) = o;
            }
        }
    }
}

extern "C" void kernel_launch(void* const* d_in, const int* in_sizes, int n_in,
                              void* d_out, int out_size)
{
    const float* x = (const float*)d_in[0];
    const float* W = (const float*)d_in[1];
    const float* b = (const float*)d_in[2];
    float* out = (float*)d_out;

    prep_W_kernel<<<256, 256>>>(W);

    cudaFuncSetAttribute(hyper_hmma_kernel,
                         cudaFuncAttributeMaxDynamicSharedMemorySize, SMEM_BYTES);
    const int nrows = in_sizes[0] / 256;
    hyper_hmma_kernel<<<nrows / 128, NT, SMEM_BYTES>>>(x, b, out);
}